// round 1
// baseline (speedup 1.0000x reference)
#include <cuda_runtime.h>
#include <cuda_bf16.h>
#include <cstdint>
#include <cstddef>

// Problem constants
#define NMAX 10000
#define EMAX 160000
#define DIN 32
#define DOUT 64
#define DHID 128
#define BFD 13
#define KDIM (DHID * DIN)   // 4096

// ---------------- scratch (device globals; no allocations allowed) ------------
__device__ int   g_is64;
__device__ int   g_deg[NMAX];
__device__ int   g_rowptr[NMAX + 1];
__device__ int   g_cursor[NMAX];
__device__ int   g_src[EMAX];
__device__ int   g_dst[EMAX];
__device__ int   g_csr_src[EMAX];
__device__ int   g_csr_eid[EMAX];
__device__ float g_h[(size_t)EMAX * DHID];          // 82 MB
__device__ float g_S[(size_t)NMAX * KDIM];          // 164 MB
__device__ float g_Sx[(size_t)NMAX * DIN];

// ---------------- dtype detection for edge_index (int64 vs int32) -------------
__global__ void detect_kernel(const void* ei) {
    if (threadIdx.x == 0 && blockIdx.x == 0) {
        const int* w = (const int*)ei;
        long long s = 0;
        #pragma unroll 8
        for (int i = 0; i < 64; i++) s += w[2 * i + 1];
        g_is64 = (s == 0) ? 1 : 0;   // int64 positive values -> all high words zero
    }
}

// ---------------- decode + degree count ---------------------------------------
__global__ void decode_count_kernel(const void* ei, int E) {
    int i = blockIdx.x * blockDim.x + threadIdx.x;
    int stride = gridDim.x * blockDim.x;
    bool is64 = (g_is64 != 0);
    for (int e = i; e < E; e += stride) {
        int s, d;
        if (is64) {
            const long long* p = (const long long*)ei;
            s = (int)p[e]; d = (int)p[E + e];
        } else {
            const int* p = (const int*)ei;
            s = p[e]; d = p[E + e];
        }
        g_src[e] = s;
        g_dst[e] = d;
        atomicAdd(&g_deg[d], 1);
    }
}

// ---------------- single-block exclusive scan over degrees --------------------
__global__ __launch_bounds__(1024) void scan_kernel(int n) {
    __shared__ int wsum[32];
    __shared__ int carry_s;
    int tid = threadIdx.x, lane = tid & 31, wid = tid >> 5;
    if (tid == 0) carry_s = 0;
    __syncthreads();
    for (int base = 0; base < n; base += 1024) {
        int i = base + tid;
        int v = (i < n) ? g_deg[i] : 0;
        int incl = v;
        #pragma unroll
        for (int d = 1; d < 32; d <<= 1) {
            int y = __shfl_up_sync(0xffffffffu, incl, d);
            if (lane >= d) incl += y;
        }
        if (lane == 31) wsum[wid] = incl;
        __syncthreads();
        if (wid == 0) {
            int s = wsum[lane];
            #pragma unroll
            for (int d = 1; d < 32; d <<= 1) {
                int y = __shfl_up_sync(0xffffffffu, s, d);
                if (lane >= d) s += y;
            }
            wsum[lane] = s;
        }
        __syncthreads();
        int excl = incl - v + ((wid > 0) ? wsum[wid - 1] : 0) + carry_s;
        if (i < n) { g_rowptr[i] = excl; g_cursor[i] = excl; }
        int total = wsum[31];
        __syncthreads();
        if (tid == 0) carry_s += total;
        __syncthreads();
    }
    if (tid == 0) g_rowptr[n] = carry_s;
}

// ---------------- scatter edges into dst-CSR ----------------------------------
__global__ void scatter_kernel(int E) {
    int i = blockIdx.x * blockDim.x + threadIdx.x;
    int stride = gridDim.x * blockDim.x;
    for (int e = i; e < E; e += stride) {
        int d = g_dst[e];
        int pos = atomicAdd(&g_cursor[d], 1);
        g_csr_src[pos] = g_src[e];
        g_csr_eid[pos] = e;
    }
}

// ---------------- h = relu(edge_attr @ W1 + b1) -------------------------------
__global__ __launch_bounds__(128) void h_kernel(const float* __restrict__ attr,
                                                const float* __restrict__ W1,
                                                const float* __restrict__ b1, int E) {
    __shared__ float w1s[BFD * DHID];
    __shared__ float b1s[DHID];
    for (int i = threadIdx.x; i < BFD * DHID; i += blockDim.x) w1s[i] = W1[i];
    if (threadIdx.x < DHID) b1s[threadIdx.x] = b1[threadIdx.x];
    __syncthreads();
    int warp = (blockIdx.x * blockDim.x + threadIdx.x) >> 5;
    int lane = threadIdx.x & 31;
    int nwarps = (gridDim.x * blockDim.x) >> 5;
    for (int e = warp; e < E; e += nwarps) {
        float a0 = b1s[lane], a1 = b1s[lane + 32], a2 = b1s[lane + 64], a3 = b1s[lane + 96];
        const float* ea = attr + (size_t)e * BFD;
        #pragma unroll
        for (int f = 0; f < BFD; f++) {
            float av = __ldg(&ea[f]);
            a0 += av * w1s[f * DHID + lane];
            a1 += av * w1s[f * DHID + lane + 32];
            a2 += av * w1s[f * DHID + lane + 64];
            a3 += av * w1s[f * DHID + lane + 96];
        }
        float* hp = g_h + (size_t)e * DHID;
        hp[lane]      = fmaxf(a0, 0.f);
        hp[lane + 32] = fmaxf(a1, 0.f);
        hp[lane + 64] = fmaxf(a2, 0.f);
        hp[lane + 96] = fmaxf(a3, 0.f);
    }
}

// ---------------- S[n,k,i] = sum_{e->n} h_e[k] * x_src[i];  Sx[n,i] -----------
__global__ __launch_bounds__(128) void sbuild_kernel(const float* __restrict__ x, int n_nodes) {
    int n = blockIdx.x;
    if (n >= n_nodes) return;
    int t = threadIdx.x;   // 0..127 == k
    __shared__ float xs[2][DIN];
    float acc[DIN];
    #pragma unroll
    for (int i = 0; i < DIN; i++) acc[i] = 0.f;
    float sxa = 0.f;
    int beg = g_rowptr[n], end = g_rowptr[n + 1];
    int buf = 0;
    for (int idx = beg; idx < end; idx++) {
        int src = g_csr_src[idx];
        int e   = g_csr_eid[idx];
        if (t < DIN) xs[buf][t] = x[(size_t)src * DIN + t];
        float hv = g_h[(size_t)e * DHID + t];
        __syncthreads();
        #pragma unroll
        for (int i = 0; i < DIN; i++) acc[i] += hv * xs[buf][i];
        if (t < DIN) sxa += xs[buf][t];
        buf ^= 1;
    }
    float4* Srow = (float4*)(g_S + (size_t)n * KDIM + t * DIN);
    #pragma unroll
    for (int i = 0; i < DIN / 4; i++)
        Srow[i] = make_float4(acc[4 * i], acc[4 * i + 1], acc[4 * i + 2], acc[4 * i + 3]);
    if (t < DIN) g_Sx[(size_t)n * DIN + t] = sxa;
}

// ---------------- out = relu(S @ W2map + Sx@b2r + x@root + bias) --------------
// W2map[ki][o] = W2[(ki>>5)*2048 + (ki&31)*64 + o]  (ki = k*32 + i)
#define MT 32
__global__ __launch_bounds__(256) void gemm_out_kernel(const float* __restrict__ W2,
                                                       const float* __restrict__ x,
                                                       const float* __restrict__ b2,
                                                       const float* __restrict__ root,
                                                       const float* __restrict__ bias,
                                                       float* __restrict__ out, int n_nodes) {
    __shared__ float As[32][MT + 1];  // [k][m]
    __shared__ float Bs[32][DOUT];    // [k][o]
    int tid = threadIdx.x;
    int tx = tid & 15, ty = tid >> 4;       // 16 x 16
    int m0 = blockIdx.x * MT;
    float acc[2][4] = {{0.f, 0.f, 0.f, 0.f}, {0.f, 0.f, 0.f, 0.f}};

    for (int k0 = 0; k0 < KDIM; k0 += 32) {
        #pragma unroll
        for (int j = 0; j < (MT * 32) / 256; j++) {
            int flat = tid + j * 256;
            int m = flat >> 5, k = flat & 31;
            int gm = m0 + m;
            As[k][m] = (gm < n_nodes) ? g_S[(size_t)gm * KDIM + k0 + k] : 0.f;
        }
        #pragma unroll
        for (int j = 0; j < 8; j++) {
            int flat = tid + j * 256;
            int k = flat >> 6, o = flat & 63;
            int ki = k0 + k;
            Bs[k][o] = W2[(size_t)(ki >> 5) * (DIN * DOUT) + (ki & 31) * DOUT + o];
        }
        __syncthreads();
        #pragma unroll
        for (int k = 0; k < 32; k++) {
            float a0 = As[k][ty * 2];
            float a1 = As[k][ty * 2 + 1];
            float4 b = *(const float4*)&Bs[k][tx * 4];
            acc[0][0] += a0 * b.x; acc[0][1] += a0 * b.y;
            acc[0][2] += a0 * b.z; acc[0][3] += a0 * b.w;
            acc[1][0] += a1 * b.x; acc[1][1] += a1 * b.y;
            acc[1][2] += a1 * b.z; acc[1][3] += a1 * b.w;
        }
        __syncthreads();
    }
    // epilogue: + Sx@b2r + x@root + bias, relu
    #pragma unroll
    for (int r = 0; r < 2; r++) {
        int n = m0 + ty * 2 + r;
        if (n >= n_nodes) continue;
        float xr[DIN], sxr[DIN];
        #pragma unroll
        for (int i = 0; i < DIN; i++) {
            xr[i]  = x[(size_t)n * DIN + i];
            sxr[i] = g_Sx[(size_t)n * DIN + i];
        }
        #pragma unroll
        for (int c = 0; c < 4; c++) {
            int o = tx * 4 + c;
            float v = acc[r][c] + bias[o];
            #pragma unroll
            for (int i = 0; i < DIN; i++) {
                v += xr[i] * __ldg(&root[i * DOUT + o]);
                v += sxr[i] * __ldg(&b2[i * DOUT + o]);
            }
            out[(size_t)n * DOUT + o] = fmaxf(v, 0.f);
        }
    }
}

// ---------------- launch ------------------------------------------------------
extern "C" void kernel_launch(void* const* d_in, const int* in_sizes, int n_in,
                              void* d_out, int out_size) {
    const float* x    = (const float*)d_in[0];
    const void*  ei   = d_in[1];
    const float* attr = (const float*)d_in[2];
    const float* W1   = (const float*)d_in[3];
    const float* b1   = (const float*)d_in[4];
    const float* W2   = (const float*)d_in[5];
    const float* b2   = (const float*)d_in[6];
    const float* root = (const float*)d_in[7];
    const float* bias = (const float*)d_in[8];
    float* out = (float*)d_out;

    int N = in_sizes[0] / DIN;
    int E = in_sizes[2] / BFD;
    if (N > NMAX) N = NMAX;
    if (E > EMAX) E = EMAX;

    void* degp = nullptr;
    cudaGetSymbolAddress(&degp, g_deg);
    cudaMemsetAsync(degp, 0, (size_t)N * sizeof(int));

    detect_kernel<<<1, 32>>>(ei);
    decode_count_kernel<<<264, 256>>>(ei, E);
    scan_kernel<<<1, 1024>>>(N);
    scatter_kernel<<<264, 256>>>(E);
    h_kernel<<<896, 128>>>(attr, W1, b1, E);
    sbuild_kernel<<<N, 128>>>(x, N);
    gemm_out_kernel<<<(N + MT - 1) / MT, 256>>>(W2, x, b2, root, bias, out, N);
}

// round 7
// speedup vs baseline: 2.0142x; 2.0142x over previous
#include <cuda_runtime.h>
#include <cuda_bf16.h>
#include <cstdint>
#include <cstddef>

// Problem constants
#define NMAX 10000
#define EMAX 160000
#define DIN 32
#define DOUT 64
#define DHID 128
#define BFD 13
#define KDIM (DHID * DIN)      // 4096
#define KTOT (KDIM + 2 * DIN)  // 4160 = S | Sx | x
#define NTILES (KTOT / 32)     // 130

// ---------------- scratch (device globals; no allocations allowed) ------------
__device__ int   g_is64;
__device__ int   g_deg[NMAX];
__device__ int   g_rowptr[NMAX + 1];
__device__ int   g_cursor[NMAX];
__device__ int   g_src[EMAX];
__device__ int   g_dst[EMAX];
__device__ int   g_csr_src[EMAX];
__device__ int   g_csr_eid[EMAX];
__device__ float g_h[(size_t)EMAX * DHID];          // 82 MB
__device__ float g_S[(size_t)NMAX * KDIM];          // 164 MB
__device__ float g_Sx[(size_t)NMAX * DIN];
__device__ float g_Wt[(size_t)DOUT * KTOT];         // B^T: [64][4160]

// ---------------- small PTX helpers -------------------------------------------
__device__ __forceinline__ uint32_t smem_to_u32(const void* p) {
    uint32_t a;
    asm("{ .reg .u64 t; cvta.to.shared.u64 t, %1; cvt.u32.u64 %0, t; }" : "=r"(a) : "l"(p));
    return a;
}
__device__ __forceinline__ float totf32(float f) {
    uint32_t o;
    asm("cvt.rna.tf32.f32 %0, %1;" : "=r"(o) : "f"(f));
    return __uint_as_float(o);
}
__device__ __forceinline__ void cp16(uint32_t saddr, const void* g) {
    asm volatile("cp.async.cg.shared.global [%0], [%1], 16;" :: "r"(saddr), "l"(g));
}
#define CP_COMMIT() asm volatile("cp.async.commit_group;" ::: "memory")

__device__ __forceinline__ void mma_tf32(float* d, const uint32_t* a, const uint32_t* b) {
    asm volatile("mma.sync.aligned.m16n8k8.row.col.f32.tf32.tf32.f32 "
        "{%0,%1,%2,%3}, {%4,%5,%6,%7}, {%8,%9}, {%0,%1,%2,%3};"
        : "+f"(d[0]), "+f"(d[1]), "+f"(d[2]), "+f"(d[3])
        : "r"(a[0]), "r"(a[1]), "r"(a[2]), "r"(a[3]), "r"(b[0]), "r"(b[1]));
}

// ---------------- dtype detection for edge_index (int64 vs int32) -------------
__global__ void detect_kernel(const void* ei) {
    if (threadIdx.x == 0 && blockIdx.x == 0) {
        const int* w = (const int*)ei;
        long long s = 0;
        #pragma unroll 8
        for (int i = 0; i < 64; i++) s += w[2 * i + 1];
        g_is64 = (s == 0) ? 1 : 0;
    }
}

// ---------------- decode + degree count ---------------------------------------
__global__ void decode_count_kernel(const void* ei, int E) {
    int i = blockIdx.x * blockDim.x + threadIdx.x;
    int stride = gridDim.x * blockDim.x;
    bool is64 = (g_is64 != 0);
    for (int e = i; e < E; e += stride) {
        int s, d;
        if (is64) {
            const long long* p = (const long long*)ei;
            s = (int)p[e]; d = (int)p[E + e];
        } else {
            const int* p = (const int*)ei;
            s = p[e]; d = p[E + e];
        }
        g_src[e] = s;
        g_dst[e] = d;
        atomicAdd(&g_deg[d], 1);
    }
}

// ---------------- single-block exclusive scan over degrees --------------------
__global__ __launch_bounds__(1024) void scan_kernel(int n) {
    __shared__ int wsum[32];
    __shared__ int carry_s;
    int tid = threadIdx.x, lane = tid & 31, wid = tid >> 5;
    if (tid == 0) carry_s = 0;
    __syncthreads();
    for (int base = 0; base < n; base += 1024) {
        int i = base + tid;
        int v = (i < n) ? g_deg[i] : 0;
        int incl = v;
        #pragma unroll
        for (int d = 1; d < 32; d <<= 1) {
            int y = __shfl_up_sync(0xffffffffu, incl, d);
            if (lane >= d) incl += y;
        }
        if (lane == 31) wsum[wid] = incl;
        __syncthreads();
        if (wid == 0) {
            int s = wsum[lane];
            #pragma unroll
            for (int d = 1; d < 32; d <<= 1) {
                int y = __shfl_up_sync(0xffffffffu, s, d);
                if (lane >= d) s += y;
            }
            wsum[lane] = s;
        }
        __syncthreads();
        int excl = incl - v + ((wid > 0) ? wsum[wid - 1] : 0) + carry_s;
        if (i < n) { g_rowptr[i] = excl; g_cursor[i] = excl; }
        int total = wsum[31];
        __syncthreads();
        if (tid == 0) carry_s += total;
        __syncthreads();
    }
    if (tid == 0) g_rowptr[n] = carry_s;
}

// ---------------- scatter edges into dst-CSR ----------------------------------
__global__ void scatter_kernel(int E) {
    int i = blockIdx.x * blockDim.x + threadIdx.x;
    int stride = gridDim.x * blockDim.x;
    for (int e = i; e < E; e += stride) {
        int d = g_dst[e];
        int pos = atomicAdd(&g_cursor[d], 1);
        g_csr_src[pos] = g_src[e];
        g_csr_eid[pos] = e;
    }
}

// ---------------- h = relu(edge_attr @ W1 + b1) -------------------------------
__global__ __launch_bounds__(128) void h_kernel(const float* __restrict__ attr,
                                                const float* __restrict__ W1,
                                                const float* __restrict__ b1, int E) {
    __shared__ float w1s[BFD * DHID];
    __shared__ float b1s[DHID];
    for (int i = threadIdx.x; i < BFD * DHID; i += blockDim.x) w1s[i] = W1[i];
    if (threadIdx.x < DHID) b1s[threadIdx.x] = b1[threadIdx.x];
    __syncthreads();
    int warp = (blockIdx.x * blockDim.x + threadIdx.x) >> 5;
    int lane = threadIdx.x & 31;
    int nwarps = (gridDim.x * blockDim.x) >> 5;
    for (int e = warp; e < E; e += nwarps) {
        float a0 = b1s[lane], a1 = b1s[lane + 32], a2 = b1s[lane + 64], a3 = b1s[lane + 96];
        const float* ea = attr + (size_t)e * BFD;
        #pragma unroll
        for (int f = 0; f < BFD; f++) {
            float av = __ldg(&ea[f]);
            a0 += av * w1s[f * DHID + lane];
            a1 += av * w1s[f * DHID + lane + 32];
            a2 += av * w1s[f * DHID + lane + 64];
            a3 += av * w1s[f * DHID + lane + 96];
        }
        float* hp = g_h + (size_t)e * DHID;
        hp[lane]      = fmaxf(a0, 0.f);
        hp[lane + 32] = fmaxf(a1, 0.f);
        hp[lane + 64] = fmaxf(a2, 0.f);
        hp[lane + 96] = fmaxf(a3, 0.f);
    }
}

// ---------------- build g_Wt[o][k] = B[k][o], B = [W2 | b2 | root] ------------
__global__ __launch_bounds__(1024) void wt_kernel(const float* __restrict__ W2,
                                                  const float* __restrict__ b2,
                                                  const float* __restrict__ root) {
    __shared__ float tile[32][33];
    int k0 = blockIdx.x * 32, n0 = blockIdx.y * 32;
    int tx = threadIdx.x, ty = threadIdx.y;
    int k = k0 + ty, n = n0 + tx;
    float v;
    if (k < KDIM)            v = W2[(size_t)k * DOUT + n];
    else if (k < KDIM + DIN) v = b2[(size_t)(k - KDIM) * DOUT + n];
    else                     v = root[(size_t)(k - KDIM - DIN) * DOUT + n];
    tile[ty][tx] = totf32(v);
    __syncthreads();
    g_Wt[(size_t)(n0 + ty) * KTOT + k0 + tx] = tile[tx][ty];
}

// ---------------- S[n,k,i] = sum_{e->n} h_e[k] * x_src[i];  Sx[n,i] -----------
__global__ __launch_bounds__(128) void sbuild_kernel(const float* __restrict__ x, int n_nodes) {
    int n = blockIdx.x;
    if (n >= n_nodes) return;
    int t = threadIdx.x;   // 0..127 == k
    __shared__ float xs[4][DIN];
    float acc[DIN];
    #pragma unroll
    for (int i = 0; i < DIN; i++) acc[i] = 0.f;
    float sxa = 0.f;
    int beg = g_rowptr[n], end = g_rowptr[n + 1];
    int idx = beg;
    for (; idx + 4 <= end; idx += 4) {
        int j = t >> 5, i = t & 31;
        int srcj = g_csr_src[idx + j];
        xs[j][i] = x[(size_t)srcj * DIN + i];
        float hv0 = g_h[(size_t)g_csr_eid[idx + 0] * DHID + t];
        float hv1 = g_h[(size_t)g_csr_eid[idx + 1] * DHID + t];
        float hv2 = g_h[(size_t)g_csr_eid[idx + 2] * DHID + t];
        float hv3 = g_h[(size_t)g_csr_eid[idx + 3] * DHID + t];
        __syncthreads();
        #pragma unroll
        for (int c = 0; c < DIN; c++)
            acc[c] += hv0 * xs[0][c] + hv1 * xs[1][c] + hv2 * xs[2][c] + hv3 * xs[3][c];
        if (t < DIN) sxa += xs[0][t] + xs[1][t] + xs[2][t] + xs[3][t];
        __syncthreads();
    }
    for (; idx < end; idx++) {
        if (t < DIN) xs[0][t] = x[(size_t)g_csr_src[idx] * DIN + t];
        float hv = g_h[(size_t)g_csr_eid[idx] * DHID + t];
        __syncthreads();
        #pragma unroll
        for (int c = 0; c < DIN; c++) acc[c] += hv * xs[0][c];
        if (t < DIN) sxa += xs[0][t];
        __syncthreads();
    }
    float4* Srow = (float4*)(g_S + (size_t)n * KDIM + t * DIN);
    #pragma unroll
    for (int i = 0; i < DIN / 4; i++)
        Srow[i] = make_float4(totf32(acc[4 * i]), totf32(acc[4 * i + 1]),
                              totf32(acc[4 * i + 2]), totf32(acc[4 * i + 3]));
    if (t < DIN) g_Sx[(size_t)n * DIN + t] = totf32(sxa);
}

// ---------------- mma.sync tf32 GEMM: out = relu([S|Sx|x] @ Wt^T + bias) ------
// Block: 64 M-rows, 64 N-cols, 8 warps each 16x32. K tiled by 32, 3-stage cp.async.
#define MT 64
#define PITCH 36              // floats per smem row (144B, 16B-aligned, bank-shifted)
#define A_STAGE (MT * PITCH)          // 2304 floats
#define B_STAGE (DOUT * PITCH)        // 2304 floats
#define STAGE_F (A_STAGE + B_STAGE)   // floats per stage
#define NS 3
#define GEMM_SMEM (NS * STAGE_F * 4)

__device__ __forceinline__ void load_tile(int t, float* sA, float* sB, uint32_t sAu, uint32_t sBu,
                                          int m0, const float* __restrict__ x, int n_nodes) {
    int tid = threadIdx.x;
    int k0 = t * 32;
    #pragma unroll
    for (int j = 0; j < 2; j++) {
        int chunk = tid + j * 256;          // 512 chunks: 64 rows x 8
        int r = chunk >> 3, c0 = (chunk & 7) * 4;
        int m = m0 + r;
        if (m >= n_nodes) m = n_nodes - 1;
        const float* g;
        if (t < 128)       g = g_S  + (size_t)m * KDIM + k0 + c0;
        else if (t == 128) g = g_Sx + (size_t)m * DIN + c0;
        else               g = x    + (size_t)m * DIN + c0;
        cp16(sAu + (r * PITCH + c0) * 4, g);
    }
    #pragma unroll
    for (int j = 0; j < 2; j++) {
        int chunk = tid + j * 256;          // 512 chunks: 64 n-rows x 8
        int nr = chunk >> 3, c0 = (chunk & 7) * 4;
        const float* g = g_Wt + (size_t)nr * KTOT + k0 + c0;
        cp16(sBu + (nr * PITCH + c0) * 4, g);
    }
}

__global__ __launch_bounds__(256) void gemm_mma_kernel(const float* __restrict__ x,
                                                       const float* __restrict__ bias,
                                                       float* __restrict__ out, int n_nodes) {
    extern __shared__ float smem[];
    uint32_t smem_u = smem_to_u32(smem);
    int tid = threadIdx.x, wid = tid >> 5, lane = tid & 31;
    int wm = wid >> 1, wn = wid & 1;     // 4 x 2 warp grid
    int m0 = blockIdx.x * MT;

    float acc[4][4];
    #pragma unroll
    for (int nt = 0; nt < 4; nt++)
        #pragma unroll
        for (int r = 0; r < 4; r++) acc[nt][r] = 0.f;

    // prologue
    #pragma unroll
    for (int t = 0; t < NS - 1; t++) {
        float* st = smem + t * STAGE_F;
        load_tile(t, st, st + A_STAGE, smem_u + t * STAGE_F * 4,
                  smem_u + (t * STAGE_F + A_STAGE) * 4, m0, x, n_nodes);
        CP_COMMIT();
    }

    int qrow = lane >> 2, qcol = lane & 3;
    for (int t = 0; t < NTILES; t++) {
        asm volatile("cp.async.wait_group %0;" :: "n"(NS - 2) : "memory");
        __syncthreads();
        int tn = t + NS - 1;
        if (tn < NTILES) {
            int s = tn % NS;
            float* st = smem + s * STAGE_F;
            load_tile(tn, st, st + A_STAGE, smem_u + s * STAGE_F * 4,
                      smem_u + (s * STAGE_F + A_STAGE) * 4, m0, x, n_nodes);
        }
        CP_COMMIT();

        const float* As = smem + (t % NS) * STAGE_F;
        const float* Bs = As + A_STAGE;
        #pragma unroll
        for (int ks = 0; ks < 4; ks++) {
            int c = ks * 8 + qcol;
            uint32_t a[4];
            {
                int r0 = wm * 16 + qrow;
                a[0] = __float_as_uint(As[r0 * PITCH + c]);
                a[1] = __float_as_uint(As[(r0 + 8) * PITCH + c]);
                a[2] = __float_as_uint(As[r0 * PITCH + c + 4]);
                a[3] = __float_as_uint(As[(r0 + 8) * PITCH + c + 4]);
            }
            #pragma unroll
            for (int nt = 0; nt < 4; nt++) {
                uint32_t b[2];
                int n0 = wn * 32 + nt * 8 + qrow;
                b[0] = __float_as_uint(Bs[n0 * PITCH + c]);
                b[1] = __float_as_uint(Bs[n0 * PITCH + c + 4]);
                mma_tf32(acc[nt], a, b);
            }
        }
        __syncthreads();
    }

    // epilogue: bias + relu, fragment layout m16n8
    #pragma unroll
    for (int nt = 0; nt < 4; nt++) {
        int o = wn * 32 + nt * 8 + qcol * 2;
        float b0 = __ldg(&bias[o]), b1 = __ldg(&bias[o + 1]);
        #pragma unroll
        for (int half = 0; half < 2; half++) {
            int n = m0 + wm * 16 + qrow + half * 8;
            if (n < n_nodes) {
                float2 v;
                v.x = fmaxf(acc[nt][2 * half + 0] + b0, 0.f);
                v.y = fmaxf(acc[nt][2 * half + 1] + b1, 0.f);
                *(float2*)(out + (size_t)n * DOUT + o) = v;
            }
        }
    }
}

// ---------------- launch ------------------------------------------------------
extern "C" void kernel_launch(void* const* d_in, const int* in_sizes, int n_in,
                              void* d_out, int out_size) {
    const float* x    = (const float*)d_in[0];
    const void*  ei   = d_in[1];
    const float* attr = (const float*)d_in[2];
    const float* W1   = (const float*)d_in[3];
    const float* b1   = (const float*)d_in[4];
    const float* W2   = (const float*)d_in[5];
    const float* b2   = (const float*)d_in[6];
    const float* root = (const float*)d_in[7];
    const float* bias = (const float*)d_in[8];
    float* out = (float*)d_out;

    int N = in_sizes[0] / DIN;
    int E = in_sizes[2] / BFD;
    if (N > NMAX) N = NMAX;
    if (E > EMAX) E = EMAX;

    void* degp = nullptr;
    cudaGetSymbolAddress(&degp, g_deg);
    cudaMemsetAsync(degp, 0, (size_t)N * sizeof(int));

    static int smem_set = 0;
    if (!smem_set) {
        cudaFuncSetAttribute(gemm_mma_kernel, cudaFuncAttributeMaxDynamicSharedMemorySize, GEMM_SMEM);
        smem_set = 1;
    }

    detect_kernel<<<1, 32>>>(ei);
    decode_count_kernel<<<264, 256>>>(ei, E);
    scan_kernel<<<1, 1024>>>(N);
    scatter_kernel<<<264, 256>>>(E);
    h_kernel<<<896, 128>>>(attr, W1, b1, E);
    wt_kernel<<<dim3(NTILES, 2), dim3(32, 32)>>>(W2, b2, root);
    sbuild_kernel<<<N, 128>>>(x, N);
    gemm_mma_kernel<<<(N + MT - 1) / MT, 256, GEMM_SMEM>>>(x, bias, out, N);
}